// round 1
// baseline (speedup 1.0000x reference)
#include <cuda_runtime.h>
#include <math.h>

#define SQ      2048
#define DMODEL  4096
#define DHEAD   128
#define NHEADS  32
#define NKV     8
#define KDIM_Q  (NHEADS*DHEAD)   /* 4096 */
#define KDIM_KV (NKV*DHEAD)      /* 1024 */

// -------- scratch (device globals: allocation-free) --------
__device__ __align__(256) float g_h[SQ*DMODEL];
__device__ __align__(256) float g_q[SQ*KDIM_Q];
__device__ __align__(256) float g_k[SQ*KDIM_KV];
__device__ __align__(256) float g_v[SQ*KDIM_KV];
__device__ __align__(256) float g_attn[SQ*DMODEL];

// ============================ RMSNorm ============================
__global__ __launch_bounds__(256) void rmsnorm_kernel(
    const float* __restrict__ x, const float* __restrict__ w, float* __restrict__ h)
{
    int row = blockIdx.x;
    const float* xr = x + (size_t)row * DMODEL;
    float ss = 0.f;
    for (int i = threadIdx.x; i < DMODEL/4; i += blockDim.x) {
        float4 v = ((const float4*)xr)[i];
        ss += v.x*v.x + v.y*v.y + v.z*v.z + v.w*v.w;
    }
    __shared__ float red[32];
    #pragma unroll
    for (int o = 16; o > 0; o >>= 1) ss += __shfl_xor_sync(0xffffffffu, ss, o);
    if ((threadIdx.x & 31) == 0) red[threadIdx.x >> 5] = ss;
    __syncthreads();
    if (threadIdx.x < 32) {
        float v = (threadIdx.x < (blockDim.x >> 5)) ? red[threadIdx.x] : 0.f;
        #pragma unroll
        for (int o = 16; o > 0; o >>= 1) v += __shfl_xor_sync(0xffffffffu, v, o);
        if (threadIdx.x == 0) red[0] = v;
    }
    __syncthreads();
    float scale = rsqrtf(red[0] / (float)DMODEL + 1e-5f);
    float* hr = h + (size_t)row * DMODEL;
    for (int i = threadIdx.x; i < DMODEL/4; i += blockDim.x) {
        float4 v  = ((const float4*)xr)[i];
        float4 wv = ((const float4*)w)[i];
        float4 o4;
        o4.x = v.x * scale * wv.x;
        o4.y = v.y * scale * wv.y;
        o4.z = v.z * scale * wv.z;
        o4.w = v.w * scale * wv.w;
        ((float4*)hr)[i] = o4;
    }
}

// ============================ SGEMM: C[M,N] = A[M,K] @ B[N,K]^T (+R) ============================
// 128x128 tile, BK=16, 256 threads, 8x8 per thread (split 4+4).
__global__ __launch_bounds__(256) void sgemm_tn(
    const float* __restrict__ A, const float* __restrict__ B,
    float* __restrict__ C, const float* __restrict__ R,
    int M, int N, int K)
{
    __shared__ float As[16][132];
    __shared__ float Bs[16][132];
    const int tid = threadIdx.x;
    const int tx = tid & 15;
    const int ty = tid >> 4;
    const int bm = blockIdx.y * 128;
    const int bn = blockIdx.x * 128;

    float acc[8][8];
    #pragma unroll
    for (int i = 0; i < 8; i++)
        #pragma unroll
        for (int j = 0; j < 8; j++) acc[i][j] = 0.f;

    const int lr = tid >> 2;          // 0..63
    const int lk = (tid & 3) << 2;    // 0,4,8,12
    const float* Ap = A + (size_t)(bm + lr) * K + lk;
    const float* Bp = B + (size_t)(bn + lr) * K + lk;

    for (int k0 = 0; k0 < K; k0 += 16) {
        float4 a0 = *(const float4*)Ap;
        float4 a1 = *(const float4*)(Ap + (size_t)64 * K);
        float4 b0 = *(const float4*)Bp;
        float4 b1 = *(const float4*)(Bp + (size_t)64 * K);
        Ap += 16; Bp += 16;
        __syncthreads();
        As[lk+0][lr]    = a0.x; As[lk+1][lr]    = a0.y; As[lk+2][lr]    = a0.z; As[lk+3][lr]    = a0.w;
        As[lk+0][lr+64] = a1.x; As[lk+1][lr+64] = a1.y; As[lk+2][lr+64] = a1.z; As[lk+3][lr+64] = a1.w;
        Bs[lk+0][lr]    = b0.x; Bs[lk+1][lr]    = b0.y; Bs[lk+2][lr]    = b0.z; Bs[lk+3][lr]    = b0.w;
        Bs[lk+0][lr+64] = b1.x; Bs[lk+1][lr+64] = b1.y; Bs[lk+2][lr+64] = b1.z; Bs[lk+3][lr+64] = b1.w;
        __syncthreads();
        #pragma unroll
        for (int kk = 0; kk < 16; kk++) {
            float4 a0v = *(const float4*)&As[kk][ty*4];
            float4 a1v = *(const float4*)&As[kk][ty*4+64];
            float4 b0v = *(const float4*)&Bs[kk][tx*4];
            float4 b1v = *(const float4*)&Bs[kk][tx*4+64];
            float av[8] = {a0v.x,a0v.y,a0v.z,a0v.w,a1v.x,a1v.y,a1v.z,a1v.w};
            float bv[8] = {b0v.x,b0v.y,b0v.z,b0v.w,b1v.x,b1v.y,b1v.z,b1v.w};
            #pragma unroll
            for (int i = 0; i < 8; i++)
                #pragma unroll
                for (int j = 0; j < 8; j++)
                    acc[i][j] = fmaf(av[i], bv[j], acc[i][j]);
        }
    }

    #pragma unroll
    for (int i = 0; i < 8; i++) {
        int row = bm + ((i < 4) ? (ty*4 + i) : (64 + ty*4 + (i - 4)));
        #pragma unroll
        for (int jh = 0; jh < 2; jh++) {
            int col = bn + tx*4 + jh*64;
            float4 r4;
            r4.x = acc[i][jh*4+0]; r4.y = acc[i][jh*4+1];
            r4.z = acc[i][jh*4+2]; r4.w = acc[i][jh*4+3];
            if (R) {
                float4 rv = *(const float4*)&R[(size_t)row * N + col];
                r4.x += rv.x; r4.y += rv.y; r4.z += rv.z; r4.w += rv.w;
            }
            *(float4*)&C[(size_t)row * N + col] = r4;
        }
    }
}

// ============================ RoPE (in-place on q and k) ============================
__global__ void rope_kernel(float* __restrict__ q, float* __restrict__ k,
                            const float* __restrict__ rc, const float* __restrict__ rs)
{
    int idx = blockIdx.x * blockDim.x + threadIdx.x;
    const int qpairs = SQ * NHEADS * (DHEAD/2);   // 4,194,304
    const int kpairs = SQ * NKV    * (DHEAD/2);   // 1,048,576
    if (idx < qpairs) {
        int p = idx & 63;
        int h = (idx >> 6) & 31;
        int s = idx >> 11;
        float c  = rc[s*DHEAD + 2*p];
        float sn = rs[s*DHEAD + 2*p];
        float* b = q + (size_t)s*KDIM_Q + h*DHEAD + 2*p;
        float x0 = b[0], x1 = b[1];
        b[0] = x0*c - x1*sn;
        b[1] = x1*c + x0*sn;
    } else if (idx < qpairs + kpairs) {
        int j = idx - qpairs;
        int p = j & 63;
        int h = (j >> 6) & 7;
        int s = j >> 9;
        float c  = rc[s*DHEAD + 2*p];
        float sn = rs[s*DHEAD + 2*p];
        float* b = k + (size_t)s*KDIM_KV + h*DHEAD + 2*p;
        float x0 = b[0], x1 = b[1];
        b[0] = x0*c - x1*sn;
        b[1] = x1*c + x0*sn;
    }
}

// ============================ Flash attention (causal GQA) ============================
#define AT_QP 130
#define AT_PP 66
#define ATT_SMEM_FLOATS (3*64*AT_QP + 64*AT_PP)
#define ATT_SMEM_BYTES  (ATT_SMEM_FLOATS * 4)

__global__ __launch_bounds__(256) void attn_kernel(
    const float* __restrict__ q, const float* __restrict__ k,
    const float* __restrict__ v, float* __restrict__ out)
{
    extern __shared__ float sm[];
    float* Qs = sm;
    float* Ks = Qs + 64*AT_QP;
    float* Vs = Ks + 64*AT_QP;
    float* Ps = Vs + 64*AT_QP;

    const int head = blockIdx.y;
    const int kvh  = head >> 2;                 // 32/8 = 4 query heads per kv head
    const int qt   = gridDim.x - 1 - blockIdx.x; // long blocks scheduled first
    const int tid  = threadIdx.x;
    const int tx   = tid & 15;
    const int ty   = tid >> 4;

    // load Q tile [64,128]
    const float* qb = q + (size_t)(qt*64)*KDIM_Q + head*DHEAD;
    for (int i = tid; i < 64*32; i += 256) {
        int r = i >> 5;
        int c = (i & 31) << 2;
        float4 vq = *(const float4*)(qb + (size_t)r*KDIM_Q + c);
        Qs[r*AT_QP + c + 0] = vq.x;
        Qs[r*AT_QP + c + 1] = vq.y;
        Qs[r*AT_QP + c + 2] = vq.z;
        Qs[r*AT_QP + c + 3] = vq.w;
    }

    float m_i[4], l_i[4], o[4][8];
    #pragma unroll
    for (int ii = 0; ii < 4; ii++) {
        m_i[ii] = -1e30f; l_i[ii] = 0.f;
        #pragma unroll
        for (int cc = 0; cc < 8; cc++) o[ii][cc] = 0.f;
    }

    const float scale = 0.08838834764831845f;  // 1/sqrt(128)

    for (int jt = 0; jt <= qt; jt++) {
        const float* kb = k + (size_t)(jt*64)*KDIM_KV + kvh*DHEAD;
        const float* vb = v + (size_t)(jt*64)*KDIM_KV + kvh*DHEAD;
        __syncthreads();   // previous iter's P/V consumers done (also publishes Qs on first iter)
        for (int i = tid; i < 64*32; i += 256) {
            int r = i >> 5;
            int c = (i & 31) << 2;
            float4 vk = *(const float4*)(kb + (size_t)r*KDIM_KV + c);
            Ks[r*AT_QP + c + 0] = vk.x; Ks[r*AT_QP + c + 1] = vk.y;
            Ks[r*AT_QP + c + 2] = vk.z; Ks[r*AT_QP + c + 3] = vk.w;
            float4 vv = *(const float4*)(vb + (size_t)r*KDIM_KV + c);
            Vs[r*AT_QP + c + 0] = vv.x; Vs[r*AT_QP + c + 1] = vv.y;
            Vs[r*AT_QP + c + 2] = vv.z; Vs[r*AT_QP + c + 3] = vv.w;
        }
        __syncthreads();

        // S = Q K^T  (rows: ty*4+ii ; cols: tx+16*jj)
        float sc[4][4];
        #pragma unroll
        for (int ii = 0; ii < 4; ii++)
            #pragma unroll
            for (int jj = 0; jj < 4; jj++) sc[ii][jj] = 0.f;

        #pragma unroll 4
        for (int d = 0; d < DHEAD; d++) {
            float qv[4], kv[4];
            #pragma unroll
            for (int ii = 0; ii < 4; ii++) qv[ii] = Qs[(ty*4+ii)*AT_QP + d];
            #pragma unroll
            for (int jj = 0; jj < 4; jj++) kv[jj] = Ks[(tx+16*jj)*AT_QP + d];
            #pragma unroll
            for (int ii = 0; ii < 4; ii++)
                #pragma unroll
                for (int jj = 0; jj < 4; jj++)
                    sc[ii][jj] = fmaf(qv[ii], kv[jj], sc[ii][jj]);
        }

        const bool diag = (jt == qt);
        #pragma unroll
        for (int ii = 0; ii < 4; ii++) {
            int rloc = ty*4 + ii;
            float rm = -1e30f;
            #pragma unroll
            for (int jj = 0; jj < 4; jj++) {
                float s = sc[ii][jj] * scale;
                if (diag && (tx + 16*jj) > rloc) s = -1e30f;
                sc[ii][jj] = s;
                rm = fmaxf(rm, s);
            }
            #pragma unroll
            for (int off = 8; off > 0; off >>= 1)
                rm = fmaxf(rm, __shfl_xor_sync(0xffffffffu, rm, off));
            float mn   = fmaxf(m_i[ii], rm);
            float corr = __expf(m_i[ii] - mn);
            float rsum = 0.f;
            #pragma unroll
            for (int jj = 0; jj < 4; jj++) {
                float p = __expf(sc[ii][jj] - mn);
                Ps[rloc*AT_PP + tx + 16*jj] = p;
                rsum += p;
            }
            #pragma unroll
            for (int off = 8; off > 0; off >>= 1)
                rsum += __shfl_xor_sync(0xffffffffu, rsum, off);
            l_i[ii] = l_i[ii] * corr + rsum;
            m_i[ii] = mn;
            #pragma unroll
            for (int cc = 0; cc < 8; cc++) o[ii][cc] *= corr;
        }
        __syncthreads();

        // O += P V   (cols: tx+16*cc)
        #pragma unroll 2
        for (int j = 0; j < 64; j++) {
            float pv[4], vvv[8];
            #pragma unroll
            for (int ii = 0; ii < 4; ii++) pv[ii] = Ps[(ty*4+ii)*AT_PP + j];
            #pragma unroll
            for (int cc = 0; cc < 8; cc++) vvv[cc] = Vs[j*AT_QP + tx + 16*cc];
            #pragma unroll
            for (int ii = 0; ii < 4; ii++)
                #pragma unroll
                for (int cc = 0; cc < 8; cc++)
                    o[ii][cc] = fmaf(pv[ii], vvv[cc], o[ii][cc]);
        }
    }

    float* ob = out + (size_t)(qt*64)*DMODEL + head*DHEAD;
    #pragma unroll
    for (int ii = 0; ii < 4; ii++) {
        float inv = 1.f / l_i[ii];
        #pragma unroll
        for (int cc = 0; cc < 8; cc++)
            ob[(ty*4+ii)*DMODEL + tx + 16*cc] = o[ii][cc] * inv;
    }
}

// ============================ launch ============================
extern "C" void kernel_launch(void* const* d_in, const int* in_sizes, int n_in,
                              void* d_out, int out_size)
{
    const float* x     = (const float*)d_in[0];
    const float* r_cos = (const float*)d_in[1];
    const float* r_sin = (const float*)d_in[2];
    /* d_in[3] mask: causal, implemented analytically */
    const float* nw    = (const float*)d_in[4];
    const float* wq    = (const float*)d_in[5];
    const float* wk    = (const float*)d_in[6];
    const float* wv    = (const float*)d_in[7];
    const float* wo    = (const float*)d_in[8];
    float* out = (float*)d_out;

    float *h, *q, *k, *v, *attn;
    cudaGetSymbolAddress((void**)&h,    g_h);
    cudaGetSymbolAddress((void**)&q,    g_q);
    cudaGetSymbolAddress((void**)&k,    g_k);
    cudaGetSymbolAddress((void**)&v,    g_v);
    cudaGetSymbolAddress((void**)&attn, g_attn);

    cudaFuncSetAttribute(attn_kernel, cudaFuncAttributeMaxDynamicSharedMemorySize, ATT_SMEM_BYTES);

    // 1. RMSNorm
    rmsnorm_kernel<<<SQ, 256>>>(x, nw, h);

    // 2-4. Q/K/V projections
    sgemm_tn<<<dim3(KDIM_Q/128,  SQ/128), 256>>>(h, wq, q, nullptr, SQ, KDIM_Q,  DMODEL);
    sgemm_tn<<<dim3(KDIM_KV/128, SQ/128), 256>>>(h, wk, k, nullptr, SQ, KDIM_KV, DMODEL);
    sgemm_tn<<<dim3(KDIM_KV/128, SQ/128), 256>>>(h, wv, v, nullptr, SQ, KDIM_KV, DMODEL);

    // 5. RoPE (q and k in one launch)
    {
        int pairs = SQ*NHEADS*(DHEAD/2) + SQ*NKV*(DHEAD/2);
        int blocks = (pairs + 255) / 256;
        rope_kernel<<<blocks, 256>>>(q, k, r_cos, r_sin);
    }

    // 6. causal GQA flash attention
    attn_kernel<<<dim3(SQ/64, NHEADS), 256, ATT_SMEM_BYTES>>>(q, k, v, attn);

    // 7. output projection + residual
    sgemm_tn<<<dim3(DMODEL/128, SQ/128), 256>>>(attn, wo, out, x, SQ, DMODEL, DMODEL);
}

// round 3
// speedup vs baseline: 2.8264x; 2.8264x over previous
#include <cuda_runtime.h>
#include <cuda_fp16.h>
#include <stdint.h>
#include <math.h>

#define SQ      2048
#define DMODEL  4096
#define DHEAD   128
#define NHEADS  32
#define NKV     8
#define KDIM_Q  (NHEADS*DHEAD)   /* 4096 */
#define KDIM_KV (NKV*DHEAD)      /* 1024 */

// -------- scratch (device globals: allocation-free) --------
__device__ __align__(256) __half g_h16[SQ*DMODEL];
__device__ __align__(256) __half g_wq16[KDIM_Q*DMODEL];
__device__ __align__(256) __half g_wk16[KDIM_KV*DMODEL];
__device__ __align__(256) __half g_wv16[KDIM_KV*DMODEL];
__device__ __align__(256) __half g_wo16[DMODEL*DMODEL];
__device__ __align__(256) __half g_attn16[SQ*DMODEL];
__device__ __align__(256) float  g_q[SQ*KDIM_Q];
__device__ __align__(256) float  g_k[SQ*KDIM_KV];
__device__ __align__(256) float  g_v[SQ*KDIM_KV];

// ============================ helpers ============================
static __device__ __forceinline__ uint32_t smem_u32(const void* p) {
    uint32_t a;
    asm("{ .reg .u64 t; cvta.to.shared.u64 t, %1; cvt.u32.u64 %0, t; }" : "=r"(a) : "l"(p));
    return a;
}
#define SWZ128(x) ((x) ^ (((x) >> 3) & 0x70))

#define CP16(s, g) \
    asm volatile("cp.async.cg.shared.global [%0], [%1], 16;" :: "r"(s), "l"(g) : "memory")
#define CP_COMMIT() asm volatile("cp.async.commit_group;" ::: "memory")
#define CP_WAIT0()  asm volatile("cp.async.wait_group 0;" ::: "memory")
#define CP_WAIT1()  asm volatile("cp.async.wait_group 1;" ::: "memory")

#define LDSM_X4(r0,r1,r2,r3,addr) \
    asm volatile("ldmatrix.sync.aligned.m8n8.x4.shared.b16 {%0,%1,%2,%3}, [%4];" \
        : "=r"(r0),"=r"(r1),"=r"(r2),"=r"(r3) : "r"(addr))
#define LDSM_X2(r0,r1,addr) \
    asm volatile("ldmatrix.sync.aligned.m8n8.x2.shared.b16 {%0,%1}, [%2];" \
        : "=r"(r0),"=r"(r1) : "r"(addr))

#define MMA16816(d, a, b) \
    asm volatile("mma.sync.aligned.m16n8k16.row.col.f32.f16.f16.f32 " \
        "{%0,%1,%2,%3}, {%4,%5,%6,%7}, {%8,%9}, {%0,%1,%2,%3};" \
        : "+f"((d)[0]),"+f"((d)[1]),"+f"((d)[2]),"+f"((d)[3]) \
        : "r"((a)[0]),"r"((a)[1]),"r"((a)[2]),"r"((a)[3]), "r"((b)[0]),"r"((b)[1]))

// ============================ fp32 -> fp16 convert ============================
__global__ __launch_bounds__(256) void cvt_f32_f16(
    const float4* __restrict__ in, __half2* __restrict__ out, int n4)
{
    int i = blockIdx.x * blockDim.x + threadIdx.x;
    if (i < n4) {
        float4 v = in[i];
        out[2*i+0] = __floats2half2_rn(v.x, v.y);
        out[2*i+1] = __floats2half2_rn(v.z, v.w);
    }
}

// ============================ RMSNorm (fp32 in, fp16 out) ============================
__global__ __launch_bounds__(256) void rmsnorm_kernel(
    const float* __restrict__ x, const float* __restrict__ w, __half* __restrict__ h)
{
    int row = blockIdx.x;
    const float* xr = x + (size_t)row * DMODEL;
    float ss = 0.f;
    for (int i = threadIdx.x; i < DMODEL/4; i += blockDim.x) {
        float4 v = ((const float4*)xr)[i];
        ss += v.x*v.x + v.y*v.y + v.z*v.z + v.w*v.w;
    }
    __shared__ float red[32];
    #pragma unroll
    for (int o = 16; o > 0; o >>= 1) ss += __shfl_xor_sync(0xffffffffu, ss, o);
    if ((threadIdx.x & 31) == 0) red[threadIdx.x >> 5] = ss;
    __syncthreads();
    if (threadIdx.x < 32) {
        float v = (threadIdx.x < (blockDim.x >> 5)) ? red[threadIdx.x] : 0.f;
        #pragma unroll
        for (int o = 16; o > 0; o >>= 1) v += __shfl_xor_sync(0xffffffffu, v, o);
        if (threadIdx.x == 0) red[0] = v;
    }
    __syncthreads();
    float scale = rsqrtf(red[0] / (float)DMODEL + 1e-5f);
    __half2* hr = (__half2*)(h + (size_t)row * DMODEL);
    for (int i = threadIdx.x; i < DMODEL/4; i += blockDim.x) {
        float4 v  = ((const float4*)xr)[i];
        float4 wv = ((const float4*)w)[i];
        hr[2*i+0] = __floats2half2_rn(v.x*scale*wv.x, v.y*scale*wv.y);
        hr[2*i+1] = __floats2half2_rn(v.z*scale*wv.z, v.w*scale*wv.w);
    }
}

// ============================ HMMA HGEMM: C[M,N] = A[M,K] @ B[N,K]^T (+R) ============================
// 128x128 CTA tile, BK=64 (128B rows, SW128 swizzle), 8 warps (64x32 each),
// cp.async double buffering, mma.sync.m16n8k16, fp32 accum.
#define HG_STAGE 32768
#define HG_SMEM  (2*HG_STAGE)

__global__ __launch_bounds__(256) void hgemm_mma(
    const __half* __restrict__ A, const __half* __restrict__ B,
    float* __restrict__ C, const float* __restrict__ R,
    int M, int N, int K)
{
    extern __shared__ char sm[];
    const uint32_t sb = smem_u32(sm);
    const int tid  = threadIdx.x;
    const int lane = tid & 31;
    const int wid  = tid >> 5;
    const int wm   = wid & 1;    // 0..1 : 64-row slice
    const int wn   = wid >> 1;   // 0..3 : 32-col slice
    const int bm = blockIdx.y * 128;
    const int bn = blockIdx.x * 128;

    const __half* Agp = A + (size_t)bm * K;
    const __half* Bgp = B + (size_t)bn * K;

    // per-thread load pattern: 4 chunks of 16B for A and for B per stage
    const int lrow = tid >> 3;        // 0..31
    const int lch  = tid & 7;         // 16B chunk within 128B row
    uint32_t swoff[4];
    #pragma unroll
    for (int j = 0; j < 4; j++)
        swoff[j] = SWZ128((uint32_t)((lrow + 32*j)*128 + lch*16));

    float acc[4][4][4];
    #pragma unroll
    for (int im = 0; im < 4; im++)
        #pragma unroll
        for (int in = 0; in < 4; in++)
            #pragma unroll
            for (int r = 0; r < 4; r++) acc[im][in][r] = 0.f;

    const int nk = K >> 6;

    // prefetch stage 0
    {
        uint32_t ab = sb, bb = sb + 16384;
        #pragma unroll
        for (int j = 0; j < 4; j++) {
            const size_t go = (size_t)(lrow + 32*j) * K + lch*8;
            CP16(ab + swoff[j], Agp + go);
            CP16(bb + swoff[j], Bgp + go);
        }
        CP_COMMIT();
    }

    // precompute ldmatrix base offsets (row parts)
    const uint32_t a_row0 = (uint32_t)(wm*64 + (lane & 15)) * 128;
    const uint32_t a_chsel = (uint32_t)(lane >> 4);            // 0/1
    const uint32_t b_row0 = (uint32_t)(wn*32 + (lane & 7)) * 128;
    const uint32_t b_chsel = (uint32_t)((lane >> 3) & 1);      // 0/1

    for (int i = 0; i < nk; i++) {
        const int b = i & 1;
        if (i + 1 < nk) {
            uint32_t ab = sb + (1-b)*HG_STAGE, bb = ab + 16384;
            const int k0 = (i+1) << 6;
            #pragma unroll
            for (int j = 0; j < 4; j++) {
                const size_t go = (size_t)(lrow + 32*j) * K + k0 + lch*8;
                CP16(ab + swoff[j], Agp + go);
                CP16(bb + swoff[j], Bgp + go);
            }
            CP_COMMIT();
            CP_WAIT1();
        } else {
            CP_WAIT0();
        }
        __syncthreads();

        const uint32_t As = sb + b*HG_STAGE;
        const uint32_t Bs = As + 16384;

        #pragma unroll
        for (int ks = 0; ks < 4; ks++) {
            uint32_t af[4][4], bf[4][2];
            #pragma unroll
            for (int im = 0; im < 4; im++) {
                uint32_t off = SWZ128(a_row0 + (uint32_t)(im*16*128) + (ks*2 + a_chsel)*16);
                LDSM_X4(af[im][0], af[im][1], af[im][2], af[im][3], As + off);
            }
            #pragma unroll
            for (int in = 0; in < 4; in++) {
                uint32_t off = SWZ128(b_row0 + (uint32_t)(in*8*128) + (ks*2 + b_chsel)*16);
                LDSM_X2(bf[in][0], bf[in][1], Bs + off);
            }
            #pragma unroll
            for (int im = 0; im < 4; im++)
                #pragma unroll
                for (int in = 0; in < 4; in++)
                    MMA16816(acc[im][in], af[im], bf[in]);
        }
        __syncthreads();
    }

    // epilogue
    #pragma unroll
    for (int im = 0; im < 4; im++) {
        const int r0 = bm + wm*64 + im*16 + (lane >> 2);
        const int r1 = r0 + 8;
        #pragma unroll
        for (int in = 0; in < 4; in++) {
            const int col = bn + wn*32 + in*8 + (lane & 3)*2;
            float2 v0 = make_float2(acc[im][in][0], acc[im][in][1]);
            float2 v1 = make_float2(acc[im][in][2], acc[im][in][3]);
            if (R) {
                const float2 q0 = *(const float2*)&R[(size_t)r0*N + col];
                const float2 q1 = *(const float2*)&R[(size_t)r1*N + col];
                v0.x += q0.x; v0.y += q0.y;
                v1.x += q1.x; v1.y += q1.y;
            }
            *(float2*)&C[(size_t)r0*N + col] = v0;
            *(float2*)&C[(size_t)r1*N + col] = v1;
        }
    }
}

// ============================ RoPE (in-place on q and k, fp32) ============================
__global__ void rope_kernel(float* __restrict__ q, float* __restrict__ k,
                            const float* __restrict__ rc, const float* __restrict__ rs)
{
    int idx = blockIdx.x * blockDim.x + threadIdx.x;
    const int qpairs = SQ * NHEADS * (DHEAD/2);
    const int kpairs = SQ * NKV    * (DHEAD/2);
    if (idx < qpairs) {
        int p = idx & 63;
        int h = (idx >> 6) & 31;
        int s = idx >> 11;
        float c  = rc[s*DHEAD + 2*p];
        float sn = rs[s*DHEAD + 2*p];
        float* b = q + (size_t)s*KDIM_Q + h*DHEAD + 2*p;
        float x0 = b[0], x1 = b[1];
        b[0] = x0*c - x1*sn;
        b[1] = x1*c + x0*sn;
    } else if (idx < qpairs + kpairs) {
        int j = idx - qpairs;
        int p = j & 63;
        int h = (j >> 6) & 7;
        int s = j >> 9;
        float c  = rc[s*DHEAD + 2*p];
        float sn = rs[s*DHEAD + 2*p];
        float* b = k + (size_t)s*KDIM_KV + h*DHEAD + 2*p;
        float x0 = b[0], x1 = b[1];
        b[0] = x0*c - x1*sn;
        b[1] = x1*c + x0*sn;
    }
}

// ============================ Flash attention (causal GQA, fp32, fp16 out) ============================
#define AT_QP 130
#define AT_PP 66
#define ATT_SMEM_FLOATS (3*64*AT_QP + 64*AT_PP)
#define ATT_SMEM_BYTES  (ATT_SMEM_FLOATS * 4)

__global__ __launch_bounds__(256) void attn_kernel(
    const float* __restrict__ q, const float* __restrict__ k,
    const float* __restrict__ v, __half* __restrict__ out)
{
    extern __shared__ float smf[];
    float* Qs = smf;
    float* Ks = Qs + 64*AT_QP;
    float* Vs = Ks + 64*AT_QP;
    float* Ps = Vs + 64*AT_QP;

    const int head = blockIdx.y;
    const int kvh  = head >> 2;
    const int qt   = gridDim.x - 1 - blockIdx.x;
    const int tid  = threadIdx.x;
    const int tx   = tid & 15;
    const int ty   = tid >> 4;

    const float* qb = q + (size_t)(qt*64)*KDIM_Q + head*DHEAD;
    for (int i = tid; i < 64*32; i += 256) {
        int r = i >> 5;
        int c = (i & 31) << 2;
        float4 vq = *(const float4*)(qb + (size_t)r*KDIM_Q + c);
        Qs[r*AT_QP + c + 0] = vq.x;
        Qs[r*AT_QP + c + 1] = vq.y;
        Qs[r*AT_QP + c + 2] = vq.z;
        Qs[r*AT_QP + c + 3] = vq.w;
    }

    float m_i[4], l_i[4], o[4][8];
    #pragma unroll
    for (int ii = 0; ii < 4; ii++) {
        m_i[ii] = -1e30f; l_i[ii] = 0.f;
        #pragma unroll
        for (int cc = 0; cc < 8; cc++) o[ii][cc] = 0.f;
    }

    const float scale = 0.08838834764831845f;

    for (int jt = 0; jt <= qt; jt++) {
        const float* kb = k + (size_t)(jt*64)*KDIM_KV + kvh*DHEAD;
        const float* vb = v + (size_t)(jt*64)*KDIM_KV + kvh*DHEAD;
        __syncthreads();
        for (int i = tid; i < 64*32; i += 256) {
            int r = i >> 5;
            int c = (i & 31) << 2;
            float4 vk = *(const float4*)(kb + (size_t)r*KDIM_KV + c);
            Ks[r*AT_QP + c + 0] = vk.x; Ks[r*AT_QP + c + 1] = vk.y;
            Ks[r*AT_QP + c + 2] = vk.z; Ks[r*AT_QP + c + 3] = vk.w;
            float4 vv = *(const float4*)(vb + (size_t)r*KDIM_KV + c);
            Vs[r*AT_QP + c + 0] = vv.x; Vs[r*AT_QP + c + 1] = vv.y;
            Vs[r*AT_QP + c + 2] = vv.z; Vs[r*AT_QP + c + 3] = vv.w;
        }
        __syncthreads();

        float sc[4][4];
        #pragma unroll
        for (int ii = 0; ii < 4; ii++)
            #pragma unroll
            for (int jj = 0; jj < 4; jj++) sc[ii][jj] = 0.f;

        #pragma unroll 4
        for (int d = 0; d < DHEAD; d++) {
            float qv[4], kv[4];
            #pragma unroll
            for (int ii = 0; ii < 4; ii++) qv[ii] = Qs[(ty*4+ii)*AT_QP + d];
            #pragma unroll
            for (int jj = 0; jj < 4; jj++) kv[jj] = Ks[(tx+16*jj)*AT_QP + d];
            #pragma unroll
            for (int ii = 0; ii < 4; ii++)
                #pragma unroll
                for (int jj = 0; jj < 4; jj++)
                    sc[ii][jj] = fmaf(qv[ii], kv[jj], sc[ii][jj]);
        }

        const bool diag = (jt == qt);
        #pragma unroll
        for (int ii = 0; ii < 4; ii++) {
            int rloc = ty*4 + ii;
            float rm = -1e30f;
            #pragma unroll
            for (int jj = 0; jj < 4; jj++) {
                float s = sc[ii][jj] * scale;
                if (diag && (tx + 16*jj) > rloc) s = -1e30f;
                sc[ii][jj] = s;
                rm = fmaxf(rm, s);
            }
            #pragma unroll
            for (int off = 8; off > 0; off >>= 1)
                rm = fmaxf(rm, __shfl_xor_sync(0xffffffffu, rm, off));
            float mn   = fmaxf(m_i[ii], rm);
            float corr = __expf(m_i[ii] - mn);
            float rsum = 0.f;
            #pragma unroll
            for (int jj = 0; jj < 4; jj++) {
                float p = __expf(sc[ii][jj] - mn);
                Ps[rloc*AT_PP + tx + 16*jj] = p;
                rsum += p;
            }
            #pragma unroll
            for (int off = 8; off > 0; off >>= 1)
                rsum += __shfl_xor_sync(0xffffffffu, rsum, off);
            l_i[ii] = l_i[ii] * corr + rsum;
            m_i[ii] = mn;
            #pragma unroll
            for (int cc = 0; cc < 8; cc++) o[ii][cc] *= corr;
        }
        __syncthreads();

        #pragma unroll 2
        for (int j = 0; j < 64; j++) {
            float pv[4], vvv[8];
            #pragma unroll
            for (int ii = 0; ii < 4; ii++) pv[ii] = Ps[(ty*4+ii)*AT_PP + j];
            #pragma unroll
            for (int cc = 0; cc < 8; cc++) vvv[cc] = Vs[j*AT_QP + tx + 16*cc];
            #pragma unroll
            for (int ii = 0; ii < 4; ii++)
                #pragma unroll
                for (int cc = 0; cc < 8; cc++)
                    o[ii][cc] = fmaf(pv[ii], vvv[cc], o[ii][cc]);
        }
    }

    __half* ob = out + (size_t)(qt*64)*DMODEL + head*DHEAD;
    #pragma unroll
    for (int ii = 0; ii < 4; ii++) {
        float inv = 1.f / l_i[ii];
        #pragma unroll
        for (int cc = 0; cc < 8; cc++)
            ob[(ty*4+ii)*DMODEL + tx + 16*cc] = __float2half_rn(o[ii][cc] * inv);
    }
}

// ============================ launch ============================
extern "C" void kernel_launch(void* const* d_in, const int* in_sizes, int n_in,
                              void* d_out, int out_size)
{
    const float* x     = (const float*)d_in[0];
    const float* r_cos = (const float*)d_in[1];
    const float* r_sin = (const float*)d_in[2];
    /* d_in[3] mask: causal, implemented analytically */
    const float* nw    = (const float*)d_in[4];
    const float* wq    = (const float*)d_in[5];
    const float* wk    = (const float*)d_in[6];
    const float* wv    = (const float*)d_in[7];
    const float* wo    = (const float*)d_in[8];
    float* out = (float*)d_out;

    __half *h16, *wq16, *wk16, *wv16, *wo16, *attn16;
    float *q, *k, *v;
    cudaGetSymbolAddress((void**)&h16,    g_h16);
    cudaGetSymbolAddress((void**)&wq16,   g_wq16);
    cudaGetSymbolAddress((void**)&wk16,   g_wk16);
    cudaGetSymbolAddress((void**)&wv16,   g_wv16);
    cudaGetSymbolAddress((void**)&wo16,   g_wo16);
    cudaGetSymbolAddress((void**)&attn16, g_attn16);
    cudaGetSymbolAddress((void**)&q,      g_q);
    cudaGetSymbolAddress((void**)&k,      g_k);
    cudaGetSymbolAddress((void**)&v,      g_v);

    cudaFuncSetAttribute(attn_kernel, cudaFuncAttributeMaxDynamicSharedMemorySize, ATT_SMEM_BYTES);
    cudaFuncSetAttribute(hgemm_mma,   cudaFuncAttributeMaxDynamicSharedMemorySize, HG_SMEM);

    // 0. weight conversions fp32 -> fp16
    {
        int n4;
        n4 = KDIM_Q*DMODEL/4;
        cvt_f32_f16<<<(n4+255)/256, 256>>>((const float4*)wq, (__half2*)wq16, n4);
        n4 = KDIM_KV*DMODEL/4;
        cvt_f32_f16<<<(n4+255)/256, 256>>>((const float4*)wk, (__half2*)wk16, n4);
        cvt_f32_f16<<<(n4+255)/256, 256>>>((const float4*)wv, (__half2*)wv16, n4);
        n4 = DMODEL*DMODEL/4;
        cvt_f32_f16<<<(n4+255)/256, 256>>>((const float4*)wo, (__half2*)wo16, n4);
    }

    // 1. RMSNorm -> fp16 activations
    rmsnorm_kernel<<<SQ, 256>>>(x, nw, h16);

    // 2-4. Q/K/V projections (HMMA)
    hgemm_mma<<<dim3(KDIM_Q/128,  SQ/128), 256, HG_SMEM>>>(h16, wq16, q, nullptr, SQ, KDIM_Q,  DMODEL);
    hgemm_mma<<<dim3(KDIM_KV/128, SQ/128), 256, HG_SMEM>>>(h16, wk16, k, nullptr, SQ, KDIM_KV, DMODEL);
    hgemm_mma<<<dim3(KDIM_KV/128, SQ/128), 256, HG_SMEM>>>(h16, wv16, v, nullptr, SQ, KDIM_KV, DMODEL);

    // 5. RoPE
    {
        int pairs = SQ*NHEADS*(DHEAD/2) + SQ*NKV*(DHEAD/2);
        rope_kernel<<<(pairs+255)/256, 256>>>(q, k, r_cos, r_sin);
    }

    // 6. causal GQA flash attention (fp32 compute, fp16 output)
    attn_kernel<<<dim3(SQ/64, NHEADS), 256, ATT_SMEM_BYTES>>>(q, k, v, attn16);

    // 7. output projection + residual (HMMA)
    hgemm_mma<<<dim3(DMODEL/128, SQ/128), 256, HG_SMEM>>>(attn16, wo16, out, x, SQ, DMODEL, DMODEL);
}

// round 4
// speedup vs baseline: 7.0609x; 2.4982x over previous
#include <cuda_runtime.h>
#include <cuda_fp16.h>
#include <stdint.h>
#include <math.h>

#define SQ      2048
#define DMODEL  4096
#define DHEAD   128
#define NHEADS  32
#define NKV     8
#define KDIM_Q  (NHEADS*DHEAD)   /* 4096 */
#define KDIM_KV (NKV*DHEAD)      /* 1024 */

// -------- scratch (device globals: allocation-free) --------
__device__ __align__(256) __half g_h16[SQ*DMODEL];
__device__ __align__(256) __half g_wq16[KDIM_Q*DMODEL];
__device__ __align__(256) __half g_wk16[KDIM_KV*DMODEL];
__device__ __align__(256) __half g_wv16[KDIM_KV*DMODEL];
__device__ __align__(256) __half g_wo16[DMODEL*DMODEL];
__device__ __align__(256) __half g_attn16[SQ*DMODEL];
__device__ __align__(256) __half g_q16[SQ*KDIM_Q];
__device__ __align__(256) __half g_k16[SQ*KDIM_KV];
__device__ __align__(256) __half g_v16[SQ*KDIM_KV];

// ============================ helpers ============================
static __device__ __forceinline__ uint32_t smem_u32(const void* p) {
    uint32_t a;
    asm("{ .reg .u64 t; cvta.to.shared.u64 t, %1; cvt.u32.u64 %0, t; }" : "=r"(a) : "l"(p));
    return a;
}
#define SWZ128(x) ((x) ^ (((x) >> 3) & 0x70))

#define CP16(s, g) \
    asm volatile("cp.async.cg.shared.global [%0], [%1], 16;" :: "r"(s), "l"(g) : "memory")
#define CP_COMMIT() asm volatile("cp.async.commit_group;" ::: "memory")
#define CP_WAIT0()  asm volatile("cp.async.wait_group 0;" ::: "memory")
#define CP_WAIT1()  asm volatile("cp.async.wait_group 1;" ::: "memory")

#define LDSM_X4(r0,r1,r2,r3,addr) \
    asm volatile("ldmatrix.sync.aligned.m8n8.x4.shared.b16 {%0,%1,%2,%3}, [%4];" \
        : "=r"(r0),"=r"(r1),"=r"(r2),"=r"(r3) : "r"(addr))
#define LDSM_X2(r0,r1,addr) \
    asm volatile("ldmatrix.sync.aligned.m8n8.x2.shared.b16 {%0,%1}, [%2];" \
        : "=r"(r0),"=r"(r1) : "r"(addr))
#define LDSM_X4T(r0,r1,r2,r3,addr) \
    asm volatile("ldmatrix.sync.aligned.m8n8.x4.trans.shared.b16 {%0,%1,%2,%3}, [%4];" \
        : "=r"(r0),"=r"(r1),"=r"(r2),"=r"(r3) : "r"(addr))

#define MMA16816(d, a, b) \
    asm volatile("mma.sync.aligned.m16n8k16.row.col.f32.f16.f16.f32 " \
        "{%0,%1,%2,%3}, {%4,%5,%6,%7}, {%8,%9}, {%0,%1,%2,%3};" \
        : "+f"((d)[0]),"+f"((d)[1]),"+f"((d)[2]),"+f"((d)[3]) \
        : "r"((a)[0]),"r"((a)[1]),"r"((a)[2]),"r"((a)[3]), "r"((b)[0]),"r"((b)[1]))

// ============================ fp32 -> fp16 convert ============================
__global__ __launch_bounds__(256) void cvt_f32_f16(
    const float4* __restrict__ in, __half2* __restrict__ out, int n4)
{
    int i = blockIdx.x * blockDim.x + threadIdx.x;
    if (i < n4) {
        float4 v = in[i];
        out[2*i+0] = __floats2half2_rn(v.x, v.y);
        out[2*i+1] = __floats2half2_rn(v.z, v.w);
    }
}

// ============================ RMSNorm (fp32 in, fp16 out) ============================
__global__ __launch_bounds__(256) void rmsnorm_kernel(
    const float* __restrict__ x, const float* __restrict__ w, __half* __restrict__ h)
{
    int row = blockIdx.x;
    const float* xr = x + (size_t)row * DMODEL;
    float ss = 0.f;
    for (int i = threadIdx.x; i < DMODEL/4; i += blockDim.x) {
        float4 v = ((const float4*)xr)[i];
        ss += v.x*v.x + v.y*v.y + v.z*v.z + v.w*v.w;
    }
    __shared__ float red[32];
    #pragma unroll
    for (int o = 16; o > 0; o >>= 1) ss += __shfl_xor_sync(0xffffffffu, ss, o);
    if ((threadIdx.x & 31) == 0) red[threadIdx.x >> 5] = ss;
    __syncthreads();
    if (threadIdx.x < 32) {
        float v = (threadIdx.x < (blockDim.x >> 5)) ? red[threadIdx.x] : 0.f;
        #pragma unroll
        for (int o = 16; o > 0; o >>= 1) v += __shfl_xor_sync(0xffffffffu, v, o);
        if (threadIdx.x == 0) red[0] = v;
    }
    __syncthreads();
    float scale = rsqrtf(red[0] / (float)DMODEL + 1e-5f);
    __half2* hr = (__half2*)(h + (size_t)row * DMODEL);
    for (int i = threadIdx.x; i < DMODEL/4; i += blockDim.x) {
        float4 v  = ((const float4*)xr)[i];
        float4 wv = ((const float4*)w)[i];
        hr[2*i+0] = __floats2half2_rn(v.x*scale*wv.x, v.y*scale*wv.y);
        hr[2*i+1] = __floats2half2_rn(v.z*scale*wv.z, v.w*scale*wv.w);
    }
}

// ============================ HMMA HGEMM: C[M,N] = A[M,K] @ B[N,K]^T (+R) ============================
#define HG_STAGE 32768
#define HG_SMEM  (2*HG_STAGE)

template<typename OutT>
__global__ __launch_bounds__(256) void hgemm_mma(
    const __half* __restrict__ A, const __half* __restrict__ B,
    OutT* __restrict__ C, const float* __restrict__ R,
    int M, int N, int K)
{
    extern __shared__ char sm[];
    const uint32_t sb = smem_u32(sm);
    const int tid  = threadIdx.x;
    const int lane = tid & 31;
    const int wid  = tid >> 5;
    const int wm   = wid & 1;
    const int wn   = wid >> 1;
    const int bm = blockIdx.y * 128;
    const int bn = blockIdx.x * 128;

    const __half* Agp = A + (size_t)bm * K;
    const __half* Bgp = B + (size_t)bn * K;

    const int lrow = tid >> 3;
    const int lch  = tid & 7;
    uint32_t swoff[4];
    #pragma unroll
    for (int j = 0; j < 4; j++)
        swoff[j] = SWZ128((uint32_t)((lrow + 32*j)*128 + lch*16));

    float acc[4][4][4];
    #pragma unroll
    for (int im = 0; im < 4; im++)
        #pragma unroll
        for (int in = 0; in < 4; in++)
            #pragma unroll
            for (int r = 0; r < 4; r++) acc[im][in][r] = 0.f;

    const int nk = K >> 6;

    {
        uint32_t ab = sb, bb = sb + 16384;
        #pragma unroll
        for (int j = 0; j < 4; j++) {
            const size_t go = (size_t)(lrow + 32*j) * K + lch*8;
            CP16(ab + swoff[j], Agp + go);
            CP16(bb + swoff[j], Bgp + go);
        }
        CP_COMMIT();
    }

    const uint32_t a_row0 = (uint32_t)(wm*64 + (lane & 15)) * 128;
    const uint32_t a_chsel = (uint32_t)(lane >> 4);
    const uint32_t b_row0 = (uint32_t)(wn*32 + (lane & 7)) * 128;
    const uint32_t b_chsel = (uint32_t)((lane >> 3) & 1);

    for (int i = 0; i < nk; i++) {
        const int b = i & 1;
        if (i + 1 < nk) {
            uint32_t ab = sb + (1-b)*HG_STAGE, bb = ab + 16384;
            const int k0 = (i+1) << 6;
            #pragma unroll
            for (int j = 0; j < 4; j++) {
                const size_t go = (size_t)(lrow + 32*j) * K + k0 + lch*8;
                CP16(ab + swoff[j], Agp + go);
                CP16(bb + swoff[j], Bgp + go);
            }
            CP_COMMIT();
            CP_WAIT1();
        } else {
            CP_WAIT0();
        }
        __syncthreads();

        const uint32_t As = sb + b*HG_STAGE;
        const uint32_t Bs = As + 16384;

        #pragma unroll
        for (int ks = 0; ks < 4; ks++) {
            uint32_t af[4][4], bf[4][2];
            #pragma unroll
            for (int im = 0; im < 4; im++) {
                uint32_t off = SWZ128(a_row0 + (uint32_t)(im*16*128) + (ks*2 + a_chsel)*16);
                LDSM_X4(af[im][0], af[im][1], af[im][2], af[im][3], As + off);
            }
            #pragma unroll
            for (int in = 0; in < 4; in++) {
                uint32_t off = SWZ128(b_row0 + (uint32_t)(in*8*128) + (ks*2 + b_chsel)*16);
                LDSM_X2(bf[in][0], bf[in][1], Bs + off);
            }
            #pragma unroll
            for (int im = 0; im < 4; im++)
                #pragma unroll
                for (int in = 0; in < 4; in++)
                    MMA16816(acc[im][in], af[im], bf[in]);
        }
        __syncthreads();
    }

    #pragma unroll
    for (int im = 0; im < 4; im++) {
        const int r0 = bm + wm*64 + im*16 + (lane >> 2);
        const int r1 = r0 + 8;
        #pragma unroll
        for (int in = 0; in < 4; in++) {
            const int col = bn + wn*32 + in*8 + (lane & 3)*2;
            if (sizeof(OutT) == 2) {
                __half2* p0 = (__half2*)((__half*)C + (size_t)r0*N + col);
                __half2* p1 = (__half2*)((__half*)C + (size_t)r1*N + col);
                *p0 = __floats2half2_rn(acc[im][in][0], acc[im][in][1]);
                *p1 = __floats2half2_rn(acc[im][in][2], acc[im][in][3]);
            } else {
                float2 v0 = make_float2(acc[im][in][0], acc[im][in][1]);
                float2 v1 = make_float2(acc[im][in][2], acc[im][in][3]);
                if (R) {
                    const float2 q0 = *(const float2*)&R[(size_t)r0*N + col];
                    const float2 q1 = *(const float2*)&R[(size_t)r1*N + col];
                    v0.x += q0.x; v0.y += q0.y;
                    v1.x += q1.x; v1.y += q1.y;
                }
                *(float2*)((float*)C + (size_t)r0*N + col) = v0;
                *(float2*)((float*)C + (size_t)r1*N + col) = v1;
            }
        }
    }
}

// ============================ RoPE (in-place on fp16 q and k) ============================
__global__ void rope_kernel(__half* __restrict__ q, __half* __restrict__ k,
                            const float* __restrict__ rc, const float* __restrict__ rs)
{
    int idx = blockIdx.x * blockDim.x + threadIdx.x;
    const int qpairs = SQ * NHEADS * (DHEAD/2);
    const int kpairs = SQ * NKV    * (DHEAD/2);
    if (idx < qpairs) {
        int p = idx & 63;
        int h = (idx >> 6) & 31;
        int s = idx >> 11;
        float c  = rc[s*DHEAD + 2*p];
        float sn = rs[s*DHEAD + 2*p];
        __half2* b = (__half2*)(q + (size_t)s*KDIM_Q + h*DHEAD + 2*p);
        float2 xv = __half22float2(*b);
        *b = __floats2half2_rn(xv.x*c - xv.y*sn, xv.y*c + xv.x*sn);
    } else if (idx < qpairs + kpairs) {
        int j = idx - qpairs;
        int p = j & 63;
        int h = (j >> 6) & 7;
        int s = j >> 9;
        float c  = rc[s*DHEAD + 2*p];
        float sn = rs[s*DHEAD + 2*p];
        __half2* b = (__half2*)(k + (size_t)s*KDIM_KV + h*DHEAD + 2*p);
        float2 xv = __half22float2(*b);
        *b = __floats2half2_rn(xv.x*c - xv.y*sn, xv.y*c + xv.x*sn);
    }
}

// ============================ HMMA flash attention (causal GQA) ============================
// CTA: 128 threads (4 warps). Tile: 64 q-rows x 64 kv. Each warp owns one m16 tile.
// SMEM: Q panels 16KB + 2 stages x (K 16KB + V 16KB) = 80KB.
#define FA_Q    0
#define FA_KV   16384
#define FA_STG  32768
#define FA_SMEM (FA_KV + 2*FA_STG)

__global__ __launch_bounds__(128) void attn_mma(
    const __half* __restrict__ q, const __half* __restrict__ k,
    const __half* __restrict__ v, __half* __restrict__ out)
{
    extern __shared__ char sm[];
    const uint32_t sb = smem_u32(sm);
    const int tid  = threadIdx.x;
    const int lane = tid & 31;
    const int wid  = tid >> 5;

    const int head = blockIdx.y;
    const int kvh  = head >> 2;
    const int qt   = gridDim.x - 1 - blockIdx.x;  // long tiles first

    const int lch  = tid & 7;     // 16B chunk in 128B panel row
    const int lr16 = tid >> 3;    // 0..15

    // ---- load Q tile [64 x 128] into 2 panels (SW128), async ----
    {
        const __half* qg = q + (size_t)(qt*64)*KDIM_Q + head*DHEAD;
        #pragma unroll
        for (int p = 0; p < 2; p++)
            #pragma unroll
            for (int j = 0; j < 4; j++) {
                int row = j*16 + lr16;
                CP16(sb + FA_Q + p*8192 + SWZ128((uint32_t)(row*128 + lch*16)),
                     qg + (size_t)row*KDIM_Q + p*64 + lch*8);
            }
        CP_COMMIT();
    }
    // ---- prefetch KV tile 0 into stage 0 ----
    {
        const __half* kg = k + kvh*DHEAD;
        const __half* vg = v + kvh*DHEAD;
        #pragma unroll
        for (int p = 0; p < 2; p++)
            #pragma unroll
            for (int j = 0; j < 4; j++) {
                int row = j*16 + lr16;
                uint32_t so = SWZ128((uint32_t)(row*128 + lch*16));
                CP16(sb + FA_KV + p*8192 + so,        kg + (size_t)row*KDIM_KV + p*64 + lch*8);
                CP16(sb + FA_KV + 16384 + p*8192 + so, vg + (size_t)row*KDIM_KV + p*64 + lch*8);
            }
        CP_COMMIT();
    }

    CP_WAIT0();
    __syncthreads();

    // ---- Q fragments (8 k-steps x 4 regs), resident for whole kernel ----
    uint32_t qf[8][4];
    {
        const uint32_t rowb = (uint32_t)(wid*16 + (lane & 15)) * 128;
        const uint32_t csel = (uint32_t)(lane >> 4) * 16;
        #pragma unroll
        for (int ks = 0; ks < 8; ks++) {
            uint32_t addr = sb + FA_Q + (ks >> 2)*8192 + SWZ128(rowb + (ks & 3)*32 + csel);
            LDSM_X4(qf[ks][0], qf[ks][1], qf[ks][2], qf[ks][3], addr);
        }
    }

    float of[16][4];
    #pragma unroll
    for (int t = 0; t < 16; t++)
        #pragma unroll
        for (int r = 0; r < 4; r++) of[t][r] = 0.f;
    float m0 = -1e30f, m1 = -1e30f, l0 = 0.f, l1 = 0.f;

    const float scale = 0.08838834764831845f;
    const int rloc0 = wid*16 + (lane >> 2);   // local q row (first)
    // K ldmatrix addressing pieces
    const uint32_t k_rsel = (uint32_t)(lane & 7) * 128;
    const uint32_t k_csel = (uint32_t)((lane >> 3) & 1) * 16;
    // V (trans) addressing pieces
    const uint32_t v_rsel = (uint32_t)(lane & 15) * 128;
    const uint32_t v_csel = (uint32_t)(lane >> 4) * 16;

    for (int jt = 0; jt <= qt; jt++) {
        const int stg = jt & 1;
        // prefetch next KV tile into the other stage (freed by trailing sync of prev iter)
        if (jt < qt) {
            const __half* kg = k + (size_t)((jt+1)*64)*KDIM_KV + kvh*DHEAD;
            const __half* vg = v + (size_t)((jt+1)*64)*KDIM_KV + kvh*DHEAD;
            const uint32_t base = sb + FA_KV + (1-stg)*FA_STG;
            #pragma unroll
            for (int p = 0; p < 2; p++)
                #pragma unroll
                for (int j = 0; j < 4; j++) {
                    int row = j*16 + lr16;
                    uint32_t so = SWZ128((uint32_t)(row*128 + lch*16));
                    CP16(base + p*8192 + so,         kg + (size_t)row*KDIM_KV + p*64 + lch*8);
                    CP16(base + 16384 + p*8192 + so, vg + (size_t)row*KDIM_KV + p*64 + lch*8);
                }
            CP_COMMIT();
            CP_WAIT1();
        } else {
            CP_WAIT0();
        }
        __syncthreads();

        const uint32_t Ks = sb + FA_KV + stg*FA_STG;
        const uint32_t Vs = Ks + 16384;

        // ---- S = Q K^T : 8 n-tiles x 8 k-steps ----
        float sf[8][4];
        #pragma unroll
        for (int nt = 0; nt < 8; nt++)
            #pragma unroll
            for (int r = 0; r < 4; r++) sf[nt][r] = 0.f;

        #pragma unroll
        for (int ks = 0; ks < 8; ks++) {
            const uint32_t pb = Ks + (ks >> 2)*8192;
            const uint32_t co = (ks & 3)*32 + k_csel;
            #pragma unroll
            for (int nt = 0; nt < 8; nt++) {
                uint32_t b0, b1;
                LDSM_X2(b0, b1, pb + SWZ128((uint32_t)(nt*8*128) + k_rsel + co));
                uint32_t bfr[2] = {b0, b1};
                MMA16816(sf[nt], qf[ks], bfr);
            }
        }

        // ---- online softmax ----
        const bool diag = (jt == qt);
        float mx0 = -1e30f, mx1 = -1e30f;
        #pragma unroll
        for (int nt = 0; nt < 8; nt++) {
            float s0 = sf[nt][0]*scale, s1 = sf[nt][1]*scale;
            float s2 = sf[nt][2]*scale, s3 = sf[nt][3]*scale;
            if (diag) {
                int c0 = nt*8 + (lane & 3)*2;
                if (c0   > rloc0)   s0 = -1e30f;
                if (c0+1 > rloc0)   s1 = -1e30f;
                if (c0   > rloc0+8) s2 = -1e30f;
                if (c0+1 > rloc0+8) s3 = -1e30f;
            }
            sf[nt][0] = s0; sf[nt][1] = s1; sf[nt][2] = s2; sf[nt][3] = s3;
            mx0 = fmaxf(mx0, fmaxf(s0, s1));
            mx1 = fmaxf(mx1, fmaxf(s2, s3));
        }
        #pragma unroll
        for (int o = 1; o <= 2; o <<= 1) {
            mx0 = fmaxf(mx0, __shfl_xor_sync(0xffffffffu, mx0, o));
            mx1 = fmaxf(mx1, __shfl_xor_sync(0xffffffffu, mx1, o));
        }
        const float mn0 = fmaxf(m0, mx0), mn1 = fmaxf(m1, mx1);
        const float cr0 = __expf(m0 - mn0), cr1 = __expf(m1 - mn1);

        uint32_t pa0[8], pa1[8];
        float la0 = 0.f, la1 = 0.f;
        #pragma unroll
        for (int nt = 0; nt < 8; nt++) {
            float p0 = __expf(sf[nt][0] - mn0), p1 = __expf(sf[nt][1] - mn0);
            float p2 = __expf(sf[nt][2] - mn1), p3 = __expf(sf[nt][3] - mn1);
            la0 += p0 + p1; la1 += p2 + p3;
            __half2 h01 = __floats2half2_rn(p0, p1);
            __half2 h23 = __floats2half2_rn(p2, p3);
            pa0[nt] = *(uint32_t*)&h01;
            pa1[nt] = *(uint32_t*)&h23;
        }
        #pragma unroll
        for (int o = 1; o <= 2; o <<= 1) {
            la0 += __shfl_xor_sync(0xffffffffu, la0, o);
            la1 += __shfl_xor_sync(0xffffffffu, la1, o);
        }
        l0 = l0*cr0 + la0;  m0 = mn0;
        l1 = l1*cr1 + la1;  m1 = mn1;
        #pragma unroll
        for (int t = 0; t < 16; t++) {
            of[t][0] *= cr0; of[t][1] *= cr0;
            of[t][2] *= cr1; of[t][3] *= cr1;
        }

        // ---- O += P V : 4 k-steps x 8 n-tile-pairs ----
        #pragma unroll
        for (int s = 0; s < 4; s++) {
            uint32_t pfr[4] = {pa0[2*s], pa1[2*s], pa0[2*s+1], pa1[2*s+1]};
            #pragma unroll
            for (int np = 0; np < 8; np++) {
                uint32_t v0, v1, v2, v3;
                uint32_t addr = Vs + (np >> 2)*8192 +
                    SWZ128((uint32_t)(s*16*128) + v_rsel + (np & 3)*32 + v_csel);
                LDSM_X4T(v0, v1, v2, v3, addr);
                uint32_t vb0[2] = {v0, v1}, vb1[2] = {v2, v3};
                MMA16816(of[2*np],   pfr, vb0);
                MMA16816(of[2*np+1], pfr, vb1);
            }
        }
        __syncthreads();   // all warps done reading this stage before it's overwritten
    }

    // ---- epilogue ----
    const float il0 = 1.f / l0, il1 = 1.f / l1;
    __half* ob = out + (size_t)(qt*64 + wid*16 + (lane >> 2))*DMODEL + head*DHEAD + (lane & 3)*2;
    #pragma unroll
    for (int t = 0; t < 16; t++) {
        *(__half2*)(ob + t*8)              = __floats2half2_rn(of[t][0]*il0, of[t][1]*il0);
        *(__half2*)(ob + 8*DMODEL + t*8)   = __floats2half2_rn(of[t][2]*il1, of[t][3]*il1);
    }
}

// ============================ launch ============================
extern "C" void kernel_launch(void* const* d_in, const int* in_sizes, int n_in,
                              void* d_out, int out_size)
{
    const float* x     = (const float*)d_in[0];
    const float* r_cos = (const float*)d_in[1];
    const float* r_sin = (const float*)d_in[2];
    /* d_in[3] mask: causal, implemented analytically */
    const float* nw    = (const float*)d_in[4];
    const float* wq    = (const float*)d_in[5];
    const float* wk    = (const float*)d_in[6];
    const float* wv    = (const float*)d_in[7];
    const float* wo    = (const float*)d_in[8];
    float* out = (float*)d_out;

    __half *h16, *wq16, *wk16, *wv16, *wo16, *attn16, *q16, *k16, *v16;
    cudaGetSymbolAddress((void**)&h16,    g_h16);
    cudaGetSymbolAddress((void**)&wq16,   g_wq16);
    cudaGetSymbolAddress((void**)&wk16,   g_wk16);
    cudaGetSymbolAddress((void**)&wv16,   g_wv16);
    cudaGetSymbolAddress((void**)&wo16,   g_wo16);
    cudaGetSymbolAddress((void**)&attn16, g_attn16);
    cudaGetSymbolAddress((void**)&q16,    g_q16);
    cudaGetSymbolAddress((void**)&k16,    g_k16);
    cudaGetSymbolAddress((void**)&v16,    g_v16);

    cudaFuncSetAttribute(hgemm_mma<float>,  cudaFuncAttributeMaxDynamicSharedMemorySize, HG_SMEM);
    cudaFuncSetAttribute(hgemm_mma<__half>, cudaFuncAttributeMaxDynamicSharedMemorySize, HG_SMEM);
    cudaFuncSetAttribute(attn_mma,          cudaFuncAttributeMaxDynamicSharedMemorySize, FA_SMEM);

    // 0. weight conversions fp32 -> fp16
    {
        int n4;
        n4 = KDIM_Q*DMODEL/4;
        cvt_f32_f16<<<(n4+255)/256, 256>>>((const float4*)wq, (__half2*)wq16, n4);
        n4 = KDIM_KV*DMODEL/4;
        cvt_f32_f16<<<(n4+255)/256, 256>>>((const float4*)wk, (__half2*)wk16, n4);
        cvt_f32_f16<<<(n4+255)/256, 256>>>((const float4*)wv, (__half2*)wv16, n4);
        n4 = DMODEL*DMODEL/4;
        cvt_f32_f16<<<(n4+255)/256, 256>>>((const float4*)wo, (__half2*)wo16, n4);
    }

    // 1. RMSNorm -> fp16 activations
    rmsnorm_kernel<<<SQ, 256>>>(x, nw, h16);

    // 2-4. Q/K/V projections (HMMA, fp16 out)
    hgemm_mma<__half><<<dim3(KDIM_Q/128,  SQ/128), 256, HG_SMEM>>>(h16, wq16, q16, nullptr, SQ, KDIM_Q,  DMODEL);
    hgemm_mma<__half><<<dim3(KDIM_KV/128, SQ/128), 256, HG_SMEM>>>(h16, wk16, k16, nullptr, SQ, KDIM_KV, DMODEL);
    hgemm_mma<__half><<<dim3(KDIM_KV/128, SQ/128), 256, HG_SMEM>>>(h16, wv16, v16, nullptr, SQ, KDIM_KV, DMODEL);

    // 5. RoPE (fp16 in/out, fp32 math)
    {
        int pairs = SQ*NHEADS*(DHEAD/2) + SQ*NKV*(DHEAD/2);
        rope_kernel<<<(pairs+255)/256, 256>>>(q16, k16, r_cos, r_sin);
    }

    // 6. causal GQA flash attention (HMMA)
    attn_mma<<<dim3(SQ/64, NHEADS), 128, FA_SMEM>>>(q16, k16, v16, attn16);

    // 7. output projection + residual (HMMA, fp32 out)
    hgemm_mma<float><<<dim3(DMODEL/128, SQ/128), 256, HG_SMEM>>>(attn16, wo16, out, x, SQ, DMODEL, DMODEL);
}